// round 16
// baseline (speedup 1.0000x reference)
#include <cuda_runtime.h>
#include <cuda_fp16.h>
#include <math.h>

#define N_NODES 50000
#define E_EDGES 800000
#define G_GRAPHS 512
#define HID 64
#define DOUT 128
#define LAYERS 3
#define NEG_SLOPE 0.2f
#define BN_EPS 1e-5f

typedef unsigned long long ull;

// ---------------- scratch (device globals; no allocation allowed) ----------------
__device__ float g_h  [N_NODES * HID];
__device__ float g_xl [N_NODES * HID];
__device__ float g_xr [N_NODES * HID];
__device__ int   g_hist[N_NODES];
__device__ int   g_off [N_NODES + 1];
__device__ int   g_cursor[N_NODES];
__device__ int   g_srcS[E_EDGES];
__device__ float g_eaS [E_EDGES * 16];
__device__ __half g_eaW [(size_t)E_EDGES * 64];   // ea @ We^T for current layer, fp16 (102.4 MB)
__device__ float g_cnt [G_GRAPHS];
__device__ int   g_flag;
__device__ int   g_done;

// ---------------- packed fp32x2 helpers (sm_103a FFMA2 — PTX only) ----------------
__device__ __forceinline__ ull pk(float x, float y) {
    ull r; asm("mov.b64 %0, {%1, %2};" : "=l"(r) : "f"(x), "f"(y)); return r;
}
__device__ __forceinline__ void upk(ull v, float& x, float& y) {
    asm("mov.b64 {%0, %1}, %2;" : "=f"(x), "=f"(y) : "l"(v));
}
__device__ __forceinline__ ull fma2(ull a, ull b, ull c) {
    ull d; asm("fma.rn.f32x2 %0, %1, %2, %3;" : "=l"(d) : "l"(a), "l"(b), "l"(c)); return d;
}

// ------- launch 1: embedding GEMM (blocks 0..781) + edge histogram (blocks 782+) -------
__global__ void emb_hist(const float* __restrict__ A, const float* __restrict__ W,
                         const float* __restrict__ bias, const int* __restrict__ ei) {
    int t = threadIdx.x;
    if (blockIdx.x >= 782) {
        int e = (blockIdx.x - 782) * 256 + t;
        if (e < E_EDGES) atomicAdd(&g_hist[ei[E_EDGES + e]], 1);
        return;
    }
    __shared__ float Ws[64][68];
    __shared__ float As[64][68];
    int row0 = blockIdx.x * 64;

    #pragma unroll
    for (int i = t; i < 4096; i += 256) { int c = i >> 6, k = i & 63; Ws[c][k] = W[i]; }
    #pragma unroll
    for (int i = t; i < 4096; i += 256) {
        int r = i >> 6, k = i & 63; int gr = row0 + r;
        As[r][k] = (gr < N_NODES) ? A[gr * 64 + k] : 0.f;
    }
    __syncthreads();

    int c  = t & 63;
    int rb = t >> 6;
    float acc[16];
    #pragma unroll
    for (int r = 0; r < 16; r++) acc[r] = 0.f;

    #pragma unroll
    for (int k4 = 0; k4 < 16; k4++) {
        float4 w4 = *(const float4*)&Ws[c][k4 * 4];
        #pragma unroll
        for (int r = 0; r < 16; r++) {
            float4 a4 = *(const float4*)&As[rb * 16 + r][k4 * 4];
            acc[r] += w4.x * a4.x + w4.y * a4.y + w4.z * a4.z + w4.w * a4.w;
        }
    }
    float bb = bias[c];
    #pragma unroll
    for (int r = 0; r < 16; r++) {
        int gr = row0 + rb * 16 + r;
        if (gr < N_NODES) g_h[gr * 64 + c] = acc[r] + bb;
    }
}

// ------- launch 2: block 0 scans hist -> offsets (and re-zeroes hist); others scatter ----
#define SCAT_BLOCKS 782           // ceil(800000/1024)
__global__ void scan_scatter(const int* __restrict__ ei, const float* __restrict__ eattr) {
    int t = threadIdx.x;           // 1024 threads
    if (blockIdx.x == 0) {
        __shared__ int sp[1024];
        const int CH = 49;         // 1024*49 = 50176 >= 50000
        int base = t * CH;
        int sum = 0;
        for (int i = 0; i < CH; i++) {
            int idx = base + i;
            if (idx < N_NODES) sum += g_hist[idx];
        }
        sp[t] = sum;
        __syncthreads();
        for (int off = 1; off < 1024; off <<= 1) {
            int v = (t >= off) ? sp[t - off] : 0;
            __syncthreads();
            sp[t] += v;
            __syncthreads();
        }
        int run = (t == 0) ? 0 : sp[t - 1];
        for (int i = 0; i < CH; i++) {
            int idx = base + i;
            if (idx < N_NODES) {
                g_off[idx] = run;
                g_cursor[idx] = run;
                run += g_hist[idx];
                g_hist[idx] = 0;          // reset for next graph replay
            }
        }
        if (t == 1023) g_off[N_NODES] = sp[1023];
        __threadfence();
        __syncthreads();
        if (t == 0) atomicExch(&g_flag, 1);
        return;
    }

    // scatter blocks: wait for offsets
    if (t == 0) { while (atomicAdd(&g_flag, 0) == 0) {} }
    __syncthreads();
    __threadfence();

    int e = (blockIdx.x - 1) * 1024 + t;
    if (e < E_EDGES) {
        int src = ei[e];
        int dst = ei[E_EDGES + e];
        int pos = atomicAdd(&g_cursor[dst], 1);
        g_srcS[pos] = src;
        const float4* s4 = (const float4*)(eattr + (size_t)e * 16);
        float4* d4 = (float4*)(g_eaS + (size_t)pos * 16);
        d4[0] = s4[0]; d4[1] = s4[1]; d4[2] = s4[2]; d4[3] = s4[3];
    }
    __syncthreads();
    if (t == 0) {
        int d = atomicAdd(&g_done, 1);
        if (d == SCAT_BLOCKS - 1) {        // last scatter block resets flags
            g_done = 0;
            atomicExch(&g_flag, 0);
        }
    }
}

// ------- per-layer: eaW[e][c] = sum_k eaS[e][k] * We[c][k], fp16 out (standalone) -------
#define EAW_EPB 64                // edges per block; 800000/64 = 12500 blocks
__global__ void gemm_eaw16(const float* __restrict__ We) {
    __shared__ float WsT[16][68];    // [k][c]
    __shared__ float4 As4[EAW_EPB][4]; // [edge r][k4] — 4 k per float4
    int t = threadIdx.x;             // 256
    int e0 = blockIdx.x * EAW_EPB;

    #pragma unroll
    for (int i = t; i < 1024; i += 256) { int c = i >> 4, k = i & 15; WsT[k][c] = We[i]; }
    #pragma unroll
    for (int i = t; i < EAW_EPB * 4; i += 256) {
        As4[i >> 2][i & 3] = *(const float4*)&g_eaS[(size_t)e0 * 16 + i * 4];
    }
    __syncthreads();

    int c2 = (t & 31) * 2;          // channel pair c2, c2+1
    int rb = t >> 5;                // warp 0..7: edges rb*8 .. rb*8+7

    ull wp[16];
    #pragma unroll
    for (int k = 0; k < 16; k++) wp[k] = *(const ull*)&WsT[k][c2];

    #pragma unroll
    for (int r = 0; r < 8; r++) {
        int e = rb * 8 + r;
        ull acc = pk(0.f, 0.f);
        #pragma unroll
        for (int q = 0; q < 4; q++) {
            float4 a = As4[e][q];           // warp-uniform LDS.128 broadcast
            acc = fma2(wp[q * 4 + 0], pk(a.x, a.x), acc);
            acc = fma2(wp[q * 4 + 1], pk(a.y, a.y), acc);
            acc = fma2(wp[q * 4 + 2], pk(a.z, a.z), acc);
            acc = fma2(wp[q * 4 + 3], pk(a.w, a.w), acc);
        }
        float lo, hi; upk(acc, lo, hi);
        *(__half2*)&g_eaW[(size_t)(e0 + e) * 64 + c2] = __floats2half2_rn(lo, hi);
    }
}

// ------- per-layer: fused xl/xr GEMM — 64-row tile, 8col×4row register tiling ----------
__global__ void gemm_xlxr(const float* __restrict__ Wl, const float* __restrict__ bl,
                          const float* __restrict__ Wr, const float* __restrict__ br) {
    __shared__ float Ws[64][132];   // [k][c]: cols 0..63 = Wl, 64..127 = Wr (pad 132 = 16B-aligned)
    __shared__ float As[64][68];    // [row][k]
    int t = threadIdx.x;            // 256
    int row0 = blockIdx.x * 64;

    #pragma unroll
    for (int i = t; i < 4096; i += 256) {
        int c = i >> 6, k = i & 63;
        Ws[k][c]      = Wl[i];
        Ws[k][64 + c] = Wr[i];
    }
    #pragma unroll
    for (int i = t; i < 4096; i += 256) {
        int r = i >> 6, k = i & 63; int gr = row0 + r;
        As[r][k] = (gr < N_NODES) ? g_h[gr * 64 + k] : 0.f;
    }
    __syncthreads();

    int tc = t & 15;                // col group: cols tc*8 .. tc*8+7
    int tr = t >> 4;                // row group: rows tr*4 .. tr*4+3

    float acc[4][8];
    #pragma unroll
    for (int r = 0; r < 4; r++)
        #pragma unroll
        for (int j = 0; j < 8; j++) acc[r][j] = 0.f;

    #pragma unroll
    for (int k4 = 0; k4 < 16; k4++) {
        float4 a[4];
        #pragma unroll
        for (int r = 0; r < 4; r++) a[r] = *(const float4*)&As[tr * 4 + r][k4 * 4];
        #pragma unroll
        for (int kk = 0; kk < 4; kk++) {
            float4 w0 = *(const float4*)&Ws[k4 * 4 + kk][tc * 8];
            float4 w1 = *(const float4*)&Ws[k4 * 4 + kk][tc * 8 + 4];
            #pragma unroll
            for (int r = 0; r < 4; r++) {
                float av = (kk == 0) ? a[r].x : (kk == 1) ? a[r].y : (kk == 2) ? a[r].z : a[r].w;
                acc[r][0] = fmaf(w0.x, av, acc[r][0]);
                acc[r][1] = fmaf(w0.y, av, acc[r][1]);
                acc[r][2] = fmaf(w0.z, av, acc[r][2]);
                acc[r][3] = fmaf(w0.w, av, acc[r][3]);
                acc[r][4] = fmaf(w1.x, av, acc[r][4]);
                acc[r][5] = fmaf(w1.y, av, acc[r][5]);
                acc[r][6] = fmaf(w1.z, av, acc[r][6]);
                acc[r][7] = fmaf(w1.w, av, acc[r][7]);
            }
        }
    }

    // bias + store (tc < 8 -> xl cols tc*8..; tc >= 8 -> xr cols tc*8-64..)
    float bias[8];
    #pragma unroll
    for (int j = 0; j < 8; j++) {
        int c = tc * 8 + j;
        bias[j] = (c < 64) ? bl[c] : br[c - 64];
    }
    float* outp = (tc < 8) ? g_xl : g_xr;
    int cbase = (tc < 8) ? tc * 8 : tc * 8 - 64;
    #pragma unroll
    for (int r = 0; r < 4; r++) {
        int gr = row0 + tr * 4 + r;
        if (gr < N_NODES) {
            float4 v0 = make_float4(acc[r][0] + bias[0], acc[r][1] + bias[1],
                                    acc[r][2] + bias[2], acc[r][3] + bias[3]);
            float4 v1 = make_float4(acc[r][4] + bias[4], acc[r][5] + bias[5],
                                    acc[r][6] + bias[6], acc[r][7] + bias[7]);
            *(float4*)&outp[gr * 64 + cbase]     = v0;
            *(float4*)&outp[gr * 64 + cbase + 4] = v1;
        }
    }
}

// ---- fused GAT layer: warp/node, half-warp = 2 edges/iter, fp16 eaW streamed ----
__global__ void gat_layer(const float* __restrict__ att,
                          const float* __restrict__ cb, const float* __restrict__ gamma,
                          const float* __restrict__ beta, const float* __restrict__ mean,
                          const float* __restrict__ var) {
    int t = threadIdx.x;             // 256 threads = 8 warps = 8 nodes
    int nid = (blockIdx.x * 256 + t) >> 5;   // grid exact: 6250*8 = 50000
    int lane = t & 31;
    int half = lane >> 4;            // 0 or 1
    int cg   = lane & 15;            // channels cg*4 .. cg*4+3

    float4 vr = *(const float4*)&g_xr[nid * 64 + cg * 4];
    float4 a4 = __ldg((const float4*)att + cg);

    int jb = g_off[nid], je = g_off[nid + 1];

    ull acc01 = pk(0.f, 0.f), acc23 = pk(0.f, 0.f);
    float accd = 0.f;

    for (int j0 = jb; j0 < je; j0 += 4) {
        int jA = j0 + half * 2;
        int jB = jA + 1;
        bool vA = (jA < je), vB = (jB < je);
        int jAc = vA ? jA : jb;
        int jBc = vB ? jB : jb;

        int sA = __ldg(&g_srcS[jAc]);
        int sB = __ldg(&g_srcS[jBc]);
        float4 vlA = *(const float4*)&g_xl[sA * 64 + cg * 4];
        float4 vlB = *(const float4*)&g_xl[sB * 64 + cg * 4];

        ull eA = __ldg((const ull*)(g_eaW + ((size_t)jAc << 6)) + cg);
        ull eB = __ldg((const ull*)(g_eaW + ((size_t)jBc << 6)) + cg);
        float2 fA01 = __half22float2(((const __half2*)&eA)[0]);
        float2 fA23 = __half22float2(((const __half2*)&eA)[1]);
        float2 fB01 = __half22float2(((const __half2*)&eB)[0]);
        float2 fB23 = __half22float2(((const __half2*)&eB)[1]);

        float a0 = vlA.x + vr.x + fA01.x;
        float a1 = vlA.y + vr.y + fA01.y;
        float a2 = vlA.z + vr.z + fA23.x;
        float a3 = vlA.w + vr.w + fA23.y;
        float b0 = vlB.x + vr.x + fB01.x;
        float b1 = vlB.y + vr.y + fB01.y;
        float b2 = vlB.z + vr.z + fB23.x;
        float b3 = vlB.w + vr.w + fB23.y;

        a0 = fmaxf(a0, NEG_SLOPE * a0); a1 = fmaxf(a1, NEG_SLOPE * a1);
        a2 = fmaxf(a2, NEG_SLOPE * a2); a3 = fmaxf(a3, NEG_SLOPE * a3);
        b0 = fmaxf(b0, NEG_SLOPE * b0); b1 = fmaxf(b1, NEG_SLOPE * b1);
        b2 = fmaxf(b2, NEG_SLOPE * b2); b3 = fmaxf(b3, NEG_SLOPE * b3);

        float pA = a0 * a4.x + a1 * a4.y + a2 * a4.z + a3 * a4.w;
        float pB = b0 * a4.x + b1 * a4.y + b2 * a4.z + b3 * a4.w;
        #pragma unroll
        for (int o = 1; o <= 8; o <<= 1) {
            pA += __shfl_xor_sync(0xffffffffu, pA, o);
            pB += __shfl_xor_sync(0xffffffffu, pB, o);
        }

        float wA = vA ? __expf(pA) : 0.f;   // logits small; stable without segment-max
        float wB = vB ? __expf(pB) : 0.f;
        accd += wA + wB;
        ull wwA = pk(wA, wA), wwB = pk(wB, wB);
        acc01 = fma2(wwA, pk(vlA.x, vlA.y), acc01);
        acc23 = fma2(wwA, pk(vlA.z, vlA.w), acc23);
        acc01 = fma2(wwB, pk(vlB.x, vlB.y), acc01);
        acc23 = fma2(wwB, pk(vlB.z, vlB.w), acc23);
    }

    float ax, ay, az, aw;
    upk(acc01, ax, ay); upk(acc23, az, aw);

    ax += __shfl_xor_sync(0xffffffffu, ax, 16);
    ay += __shfl_xor_sync(0xffffffffu, ay, 16);
    az += __shfl_xor_sync(0xffffffffu, az, 16);
    aw += __shfl_xor_sync(0xffffffffu, aw, 16);
    accd += __shfl_xor_sync(0xffffffffu, accd, 16);

    if (half == 0) {
        float inv = 1.f / (accd + 1e-16f);
        float4 b4  = __ldg((const float4*)cb + cg);
        float4 mu4 = __ldg((const float4*)mean + cg);
        float4 v4  = __ldg((const float4*)var + cg);
        float4 gm4 = __ldg((const float4*)gamma + cg);
        float4 bt4 = __ldg((const float4*)beta + cg);
        float o[4] = {ax * inv + b4.x, ay * inv + b4.y,
                      az * inv + b4.z, aw * inv + b4.w};
        float mu[4] = {mu4.x, mu4.y, mu4.z, mu4.w};
        float vv[4] = {v4.x, v4.y, v4.z, v4.w};
        float gm[4] = {gm4.x, gm4.y, gm4.z, gm4.w};
        float bt[4] = {bt4.x, bt4.y, bt4.z, bt4.w};
        #pragma unroll
        for (int q = 0; q < 4; q++) {
            float z = (o[q] - mu[q]) * rsqrtf(vv[q] + BN_EPS) * gm[q] + bt[q];
            o[q] = 0.5f * z * (1.f + erff(z * 0.70710678118654752f));
        }
        float4 h = *(float4*)&g_h[nid * 64 + cg * 4];
        h.x += o[0]; h.y += o[1]; h.z += o[2]; h.w += o[3];
        *(float4*)&g_h[nid * 64 + cg * 4] = h;
    }
}

// ---------------- pooling ----------------
__global__ void init_pool(float* __restrict__ out) {
    int idx = blockIdx.x * blockDim.x + threadIdx.x;
    if (idx < G_GRAPHS * DOUT) out[idx] = 0.f;
    if (idx < G_GRAPHS) g_cnt[idx] = 0.f;
}

// lin projection fused with pooled sum AND node counting
__global__ void lin_pool(const float* __restrict__ W, const float* __restrict__ bias,
                         const int* __restrict__ batch, float* __restrict__ pooled) {
    __shared__ float Ws[128][68];
    __shared__ float As[32][68];
    int t = threadIdx.x;            // 256
    int row0 = blockIdx.x * 32;

    for (int i = t; i < 128 * 64; i += 256) { int c = i >> 6, k = i & 63; Ws[c][k] = W[i]; }
    for (int i = t; i < 32 * 64; i += 256) {
        int r = i >> 6, k = i & 63; int gr = row0 + r;
        As[r][k] = (gr < N_NODES) ? g_h[gr * 64 + k] : 0.f;
    }
    __syncthreads();

    int c  = t & 127;
    int rb = t >> 7;
    float acc[16];
    #pragma unroll
    for (int r = 0; r < 16; r++) acc[r] = 0.f;

    #pragma unroll
    for (int k4 = 0; k4 < 16; k4++) {
        float4 w4 = *(const float4*)&Ws[c][k4 * 4];
        #pragma unroll
        for (int r = 0; r < 16; r++) {
            float4 a4 = *(const float4*)&As[rb * 16 + r][k4 * 4];
            acc[r] += w4.x * a4.x + w4.y * a4.y + w4.z * a4.z + w4.w * a4.w;
        }
    }
    float bb = bias[c];
    #pragma unroll
    for (int r = 0; r < 16; r++) {
        int gr = row0 + rb * 16 + r;
        if (gr < N_NODES) {
            atomicAdd(&pooled[batch[gr] * DOUT + c], acc[r] + bb);
            if (c == 0) atomicAdd(&g_cnt[batch[gr]], 1.f);
        }
    }
}

__global__ void finalize(float* __restrict__ out) {
    int idx = blockIdx.x * blockDim.x + threadIdx.x;
    if (idx >= G_GRAPHS * DOUT) return;
    out[idx] /= fmaxf(g_cnt[idx >> 7], 1.f);
}

// ---------------- launch ----------------
extern "C" void kernel_launch(void* const* d_in, const int* in_sizes, int n_in,
                              void* d_out, int out_size) {
    const float* x         = (const float*)d_in[0];
    const int*   ei        = (const int*)  d_in[1];
    const float* eattr     = (const float*)d_in[2];
    const int*   batch     = (const int*)  d_in[3];
    const float* emb_W     = (const float*)d_in[4];
    const float* emb_b     = (const float*)d_in[5];
    const float* Wl        = (const float*)d_in[6];
    const float* bl        = (const float*)d_in[7];
    const float* Wr        = (const float*)d_in[8];
    const float* br        = (const float*)d_in[9];
    const float* We        = (const float*)d_in[10];
    const float* att       = (const float*)d_in[11];
    const float* conv_bias = (const float*)d_in[12];
    const float* gamma     = (const float*)d_in[13];
    const float* beta      = (const float*)d_in[14];
    const float* mean      = (const float*)d_in[15];
    const float* var       = (const float*)d_in[16];
    const float* lin_W     = (const float*)d_in[17];
    const float* lin_b     = (const float*)d_in[18];
    float* out = (float*)d_out;

    const int XLR_BLOCKS = (N_NODES + 63) / 64;            // 782 (64-row tiles)
    const int GAT_BLOCKS = N_NODES / 8;                    // 6250
    const int EAW_BLOCKS = E_EDGES / EAW_EPB;              // 12500

    emb_hist<<<782 + 3125, 256>>>(x, emb_W, emb_b, ei);
    scan_scatter<<<1 + SCAT_BLOCKS, 1024>>>(ei, eattr);

    for (int l = 0; l < LAYERS; l++) {
        gemm_eaw16<<<EAW_BLOCKS, 256>>>(We + l * 1024);
        gemm_xlxr<<<XLR_BLOCKS, 256>>>(Wl + l * 4096, bl + l * 64, Wr + l * 4096, br + l * 64);
        gat_layer<<<GAT_BLOCKS, 256>>>(att + l * 64, conv_bias + l * 64,
                                       gamma + l * 64, beta + l * 64, mean + l * 64, var + l * 64);
    }

    init_pool<<<(G_GRAPHS * DOUT + 255) / 256, 256>>>(out);
    lin_pool<<<(N_NODES + 31) / 32, 256>>>(lin_W, lin_b, batch, out);
    finalize<<<(G_GRAPHS * DOUT + 255) / 256, 256>>>(out);
}

// round 17
// speedup vs baseline: 1.0329x; 1.0329x over previous
#include <cuda_runtime.h>
#include <cuda_fp16.h>
#include <math.h>

#define N_NODES 50000
#define E_EDGES 800000
#define G_GRAPHS 512
#define HID 64
#define DOUT 128
#define LAYERS 3
#define NEG_SLOPE 0.2f
#define BN_EPS 1e-5f

typedef unsigned long long ull;

// ---------------- scratch (device globals; no allocation allowed) ----------------
__device__ float g_h  [N_NODES * HID];
__device__ float g_xl [N_NODES * HID];
__device__ float g_xr [N_NODES * HID];
__device__ int   g_hist[N_NODES];
__device__ int   g_off [N_NODES + 1];
__device__ int   g_cursor[N_NODES];
__device__ int   g_srcS[E_EDGES];
__device__ float g_eaS [E_EDGES * 16];
__device__ __half g_eaW [(size_t)E_EDGES * 64];   // ea @ We^T for current layer, fp16 (102.4 MB)
__device__ float g_cnt [G_GRAPHS];
__device__ int   g_flag;
__device__ int   g_done;

// ---------------- packed fp32x2 helpers (sm_103a FFMA2 — PTX only) ----------------
__device__ __forceinline__ ull pk(float x, float y) {
    ull r; asm("mov.b64 %0, {%1, %2};" : "=l"(r) : "f"(x), "f"(y)); return r;
}
__device__ __forceinline__ void upk(ull v, float& x, float& y) {
    asm("mov.b64 {%0, %1}, %2;" : "=f"(x), "=f"(y) : "l"(v));
}
__device__ __forceinline__ ull fma2(ull a, ull b, ull c) {
    ull d; asm("fma.rn.f32x2 %0, %1, %2, %3;" : "=l"(d) : "l"(a), "l"(b), "l"(c)); return d;
}

// ------- launch 1: embedding GEMM (blocks 0..781) + edge histogram + out-zero (782+) ----
__global__ void emb_hist(const float* __restrict__ A, const float* __restrict__ W,
                         const float* __restrict__ bias, const int* __restrict__ ei,
                         float* __restrict__ out) {
    int t = threadIdx.x;
    if (blockIdx.x >= 782) {
        int e = (blockIdx.x - 782) * 256 + t;
        if (e < E_EDGES) atomicAdd(&g_hist[ei[E_EDGES + e]], 1);
        if (e < G_GRAPHS * DOUT) out[e] = 0.f;     // zero pooled output early
        if (e < G_GRAPHS) g_cnt[e] = 0.f;
        return;
    }
    __shared__ float Ws[64][68];
    __shared__ float As[64][68];
    int row0 = blockIdx.x * 64;

    #pragma unroll
    for (int i = t; i < 4096; i += 256) { int c = i >> 6, k = i & 63; Ws[c][k] = W[i]; }
    #pragma unroll
    for (int i = t; i < 4096; i += 256) {
        int r = i >> 6, k = i & 63; int gr = row0 + r;
        As[r][k] = (gr < N_NODES) ? A[gr * 64 + k] : 0.f;
    }
    __syncthreads();

    int c  = t & 63;
    int rb = t >> 6;
    float acc[16];
    #pragma unroll
    for (int r = 0; r < 16; r++) acc[r] = 0.f;

    #pragma unroll
    for (int k4 = 0; k4 < 16; k4++) {
        float4 w4 = *(const float4*)&Ws[c][k4 * 4];
        #pragma unroll
        for (int r = 0; r < 16; r++) {
            float4 a4 = *(const float4*)&As[rb * 16 + r][k4 * 4];
            acc[r] += w4.x * a4.x + w4.y * a4.y + w4.z * a4.z + w4.w * a4.w;
        }
    }
    float bb = bias[c];
    #pragma unroll
    for (int r = 0; r < 16; r++) {
        int gr = row0 + rb * 16 + r;
        if (gr < N_NODES) g_h[gr * 64 + c] = acc[r] + bb;
    }
}

// ------- launch 2: block 0 scans hist -> offsets (and re-zeroes hist); others scatter ----
#define SCAT_BLOCKS 782           // ceil(800000/1024)
__global__ void scan_scatter(const int* __restrict__ ei, const float* __restrict__ eattr) {
    int t = threadIdx.x;           // 1024 threads
    if (blockIdx.x == 0) {
        __shared__ int sp[1024];
        const int CH = 49;         // 1024*49 = 50176 >= 50000
        int base = t * CH;
        int sum = 0;
        for (int i = 0; i < CH; i++) {
            int idx = base + i;
            if (idx < N_NODES) sum += g_hist[idx];
        }
        sp[t] = sum;
        __syncthreads();
        for (int off = 1; off < 1024; off <<= 1) {
            int v = (t >= off) ? sp[t - off] : 0;
            __syncthreads();
            sp[t] += v;
            __syncthreads();
        }
        int run = (t == 0) ? 0 : sp[t - 1];
        for (int i = 0; i < CH; i++) {
            int idx = base + i;
            if (idx < N_NODES) {
                g_off[idx] = run;
                g_cursor[idx] = run;
                run += g_hist[idx];
                g_hist[idx] = 0;          // reset for next graph replay
            }
        }
        if (t == 1023) g_off[N_NODES] = sp[1023];
        __threadfence();
        __syncthreads();
        if (t == 0) atomicExch(&g_flag, 1);
        return;
    }

    // scatter blocks: wait for offsets
    if (t == 0) { while (atomicAdd(&g_flag, 0) == 0) {} }
    __syncthreads();
    __threadfence();

    int e = (blockIdx.x - 1) * 1024 + t;
    if (e < E_EDGES) {
        int src = ei[e];
        int dst = ei[E_EDGES + e];
        int pos = atomicAdd(&g_cursor[dst], 1);
        g_srcS[pos] = src;
        const float4* s4 = (const float4*)(eattr + (size_t)e * 16);
        float4* d4 = (float4*)(g_eaS + (size_t)pos * 16);
        d4[0] = s4[0]; d4[1] = s4[1]; d4[2] = s4[2]; d4[3] = s4[3];
    }
    __syncthreads();
    if (t == 0) {
        int d = atomicAdd(&g_done, 1);
        if (d == SCAT_BLOCKS - 1) {        // last scatter block resets flags
            g_done = 0;
            atomicExch(&g_flag, 0);
        }
    }
}

// ------- per-layer: eaW[e][c] = sum_k eaS[e][k] * We[c][k], fp16 out (standalone) -------
#define EAW_EPB 64                // edges per block; 800000/64 = 12500 blocks
__global__ void gemm_eaw16(const float* __restrict__ We) {
    __shared__ float WsT[16][68];    // [k][c]
    __shared__ float4 As4[EAW_EPB][4]; // [edge r][k4] — 4 k per float4
    int t = threadIdx.x;             // 256
    int e0 = blockIdx.x * EAW_EPB;

    #pragma unroll
    for (int i = t; i < 1024; i += 256) { int c = i >> 4, k = i & 15; WsT[k][c] = We[i]; }
    #pragma unroll
    for (int i = t; i < EAW_EPB * 4; i += 256) {
        As4[i >> 2][i & 3] = *(const float4*)&g_eaS[(size_t)e0 * 16 + i * 4];
    }
    __syncthreads();

    int c2 = (t & 31) * 2;          // channel pair c2, c2+1
    int rb = t >> 5;                // warp 0..7: edges rb*8 .. rb*8+7

    ull wp[16];
    #pragma unroll
    for (int k = 0; k < 16; k++) wp[k] = *(const ull*)&WsT[k][c2];

    #pragma unroll
    for (int r = 0; r < 8; r++) {
        int e = rb * 8 + r;
        ull acc = pk(0.f, 0.f);
        #pragma unroll
        for (int q = 0; q < 4; q++) {
            float4 a = As4[e][q];           // warp-uniform LDS.128 broadcast
            acc = fma2(wp[q * 4 + 0], pk(a.x, a.x), acc);
            acc = fma2(wp[q * 4 + 1], pk(a.y, a.y), acc);
            acc = fma2(wp[q * 4 + 2], pk(a.z, a.z), acc);
            acc = fma2(wp[q * 4 + 3], pk(a.w, a.w), acc);
        }
        float lo, hi; upk(acc, lo, hi);
        *(__half2*)&g_eaW[(size_t)(e0 + e) * 64 + c2] = __floats2half2_rn(lo, hi);
    }
}

// ---- per-layer: fused xl/xr GEMM — persistent weight tile, conflict-free 4+4 cols ----
#define XLR_TILES 782             // ceil(50000/64)
#define XLR_GRID  296
__global__ void gemm_xlxr(const float* __restrict__ Wl, const float* __restrict__ bl,
                          const float* __restrict__ Wr, const float* __restrict__ br) {
    __shared__ float Ws[64][132];   // [k][c]: c<64 Wl, c>=64 Wr (132 = 16B-aligned pad)
    __shared__ float As[64][68];    // [row][k]
    int t = threadIdx.x;            // 256

    #pragma unroll
    for (int i = t; i < 4096; i += 256) {
        int c = i >> 6, k = i & 63;
        Ws[k][c]      = Wl[i];
        Ws[k][64 + c] = Wr[i];
    }

    int tc = t & 15;                // col group: cols tc*4..+3 of BOTH Wl and Wr
    int tr = t >> 4;                // row group: rows tr*4..+3 (16 groups × 4 = 64)

    float4 bL = *(const float4*)&bl[tc * 4];
    float4 bR = *(const float4*)&br[tc * 4];

    for (int tile = blockIdx.x; tile < XLR_TILES; tile += XLR_GRID) {
        int row0 = tile * 64;
        __syncthreads();            // previous-iter readers done (also orders Ws fill, iter 0)
        #pragma unroll
        for (int i = t; i < 4096; i += 256) {
            int r = i >> 6, k = i & 63; int gr = row0 + r;
            As[r][k] = (gr < N_NODES) ? g_h[gr * 64 + k] : 0.f;
        }
        __syncthreads();

        float accL[4][4], accR[4][4];
        #pragma unroll
        for (int r = 0; r < 4; r++)
            #pragma unroll
            for (int j = 0; j < 4; j++) { accL[r][j] = 0.f; accR[r][j] = 0.f; }

        #pragma unroll
        for (int k4 = 0; k4 < 16; k4++) {
            float4 a[4];
            #pragma unroll
            for (int r = 0; r < 4; r++) a[r] = *(const float4*)&As[tr * 4 + r][k4 * 4];
            #pragma unroll
            for (int kk = 0; kk < 4; kk++) {
                float4 w0 = *(const float4*)&Ws[k4 * 4 + kk][tc * 4];       // conflict-free
                float4 w1 = *(const float4*)&Ws[k4 * 4 + kk][64 + tc * 4];  // conflict-free
                #pragma unroll
                for (int r = 0; r < 4; r++) {
                    float av = (kk == 0) ? a[r].x : (kk == 1) ? a[r].y
                             : (kk == 2) ? a[r].z : a[r].w;
                    accL[r][0] = fmaf(w0.x, av, accL[r][0]);
                    accL[r][1] = fmaf(w0.y, av, accL[r][1]);
                    accL[r][2] = fmaf(w0.z, av, accL[r][2]);
                    accL[r][3] = fmaf(w0.w, av, accL[r][3]);
                    accR[r][0] = fmaf(w1.x, av, accR[r][0]);
                    accR[r][1] = fmaf(w1.y, av, accR[r][1]);
                    accR[r][2] = fmaf(w1.z, av, accR[r][2]);
                    accR[r][3] = fmaf(w1.w, av, accR[r][3]);
                }
            }
        }

        #pragma unroll
        for (int r = 0; r < 4; r++) {
            int gr = row0 + tr * 4 + r;
            if (gr < N_NODES) {
                *(float4*)&g_xl[gr * 64 + tc * 4] =
                    make_float4(accL[r][0] + bL.x, accL[r][1] + bL.y,
                                accL[r][2] + bL.z, accL[r][3] + bL.w);
                *(float4*)&g_xr[gr * 64 + tc * 4] =
                    make_float4(accR[r][0] + bR.x, accR[r][1] + bR.y,
                                accR[r][2] + bR.z, accR[r][3] + bR.w);
            }
        }
    }
}

// ---- fused GAT layer: warp/node, half-warp = 2 edges/iter, fp16 eaW streamed ----
__global__ void gat_layer(const float* __restrict__ att,
                          const float* __restrict__ cb, const float* __restrict__ gamma,
                          const float* __restrict__ beta, const float* __restrict__ mean,
                          const float* __restrict__ var) {
    int t = threadIdx.x;             // 256 threads = 8 warps = 8 nodes
    int nid = (blockIdx.x * 256 + t) >> 5;   // grid exact: 6250*8 = 50000
    int lane = t & 31;
    int half = lane >> 4;            // 0 or 1
    int cg   = lane & 15;            // channels cg*4 .. cg*4+3

    float4 vr = *(const float4*)&g_xr[nid * 64 + cg * 4];
    float4 a4 = __ldg((const float4*)att + cg);

    int jb = g_off[nid], je = g_off[nid + 1];

    ull acc01 = pk(0.f, 0.f), acc23 = pk(0.f, 0.f);
    float accd = 0.f;

    for (int j0 = jb; j0 < je; j0 += 4) {
        int jA = j0 + half * 2;
        int jB = jA + 1;
        bool vA = (jA < je), vB = (jB < je);
        int jAc = vA ? jA : jb;
        int jBc = vB ? jB : jb;

        int sA = __ldg(&g_srcS[jAc]);
        int sB = __ldg(&g_srcS[jBc]);
        float4 vlA = *(const float4*)&g_xl[sA * 64 + cg * 4];
        float4 vlB = *(const float4*)&g_xl[sB * 64 + cg * 4];

        ull eA = __ldg((const ull*)(g_eaW + ((size_t)jAc << 6)) + cg);
        ull eB = __ldg((const ull*)(g_eaW + ((size_t)jBc << 6)) + cg);
        float2 fA01 = __half22float2(((const __half2*)&eA)[0]);
        float2 fA23 = __half22float2(((const __half2*)&eA)[1]);
        float2 fB01 = __half22float2(((const __half2*)&eB)[0]);
        float2 fB23 = __half22float2(((const __half2*)&eB)[1]);

        float a0 = vlA.x + vr.x + fA01.x;
        float a1 = vlA.y + vr.y + fA01.y;
        float a2 = vlA.z + vr.z + fA23.x;
        float a3 = vlA.w + vr.w + fA23.y;
        float b0 = vlB.x + vr.x + fB01.x;
        float b1 = vlB.y + vr.y + fB01.y;
        float b2 = vlB.z + vr.z + fB23.x;
        float b3 = vlB.w + vr.w + fB23.y;

        a0 = fmaxf(a0, NEG_SLOPE * a0); a1 = fmaxf(a1, NEG_SLOPE * a1);
        a2 = fmaxf(a2, NEG_SLOPE * a2); a3 = fmaxf(a3, NEG_SLOPE * a3);
        b0 = fmaxf(b0, NEG_SLOPE * b0); b1 = fmaxf(b1, NEG_SLOPE * b1);
        b2 = fmaxf(b2, NEG_SLOPE * b2); b3 = fmaxf(b3, NEG_SLOPE * b3);

        float pA = a0 * a4.x + a1 * a4.y + a2 * a4.z + a3 * a4.w;
        float pB = b0 * a4.x + b1 * a4.y + b2 * a4.z + b3 * a4.w;
        #pragma unroll
        for (int o = 1; o <= 8; o <<= 1) {
            pA += __shfl_xor_sync(0xffffffffu, pA, o);
            pB += __shfl_xor_sync(0xffffffffu, pB, o);
        }

        float wA = vA ? __expf(pA) : 0.f;   // logits small; stable without segment-max
        float wB = vB ? __expf(pB) : 0.f;
        accd += wA + wB;
        ull wwA = pk(wA, wA), wwB = pk(wB, wB);
        acc01 = fma2(wwA, pk(vlA.x, vlA.y), acc01);
        acc23 = fma2(wwA, pk(vlA.z, vlA.w), acc23);
        acc01 = fma2(wwB, pk(vlB.x, vlB.y), acc01);
        acc23 = fma2(wwB, pk(vlB.z, vlB.w), acc23);
    }

    float ax, ay, az, aw;
    upk(acc01, ax, ay); upk(acc23, az, aw);

    ax += __shfl_xor_sync(0xffffffffu, ax, 16);
    ay += __shfl_xor_sync(0xffffffffu, ay, 16);
    az += __shfl_xor_sync(0xffffffffu, az, 16);
    aw += __shfl_xor_sync(0xffffffffu, aw, 16);
    accd += __shfl_xor_sync(0xffffffffu, accd, 16);

    if (half == 0) {
        float inv = 1.f / (accd + 1e-16f);
        float4 b4  = __ldg((const float4*)cb + cg);
        float4 mu4 = __ldg((const float4*)mean + cg);
        float4 v4  = __ldg((const float4*)var + cg);
        float4 gm4 = __ldg((const float4*)gamma + cg);
        float4 bt4 = __ldg((const float4*)beta + cg);
        float o[4] = {ax * inv + b4.x, ay * inv + b4.y,
                      az * inv + b4.z, aw * inv + b4.w};
        float mu[4] = {mu4.x, mu4.y, mu4.z, mu4.w};
        float vv[4] = {v4.x, v4.y, v4.z, v4.w};
        float gm[4] = {gm4.x, gm4.y, gm4.z, gm4.w};
        float bt[4] = {bt4.x, bt4.y, bt4.z, bt4.w};
        #pragma unroll
        for (int q = 0; q < 4; q++) {
            float z = (o[q] - mu[q]) * rsqrtf(vv[q] + BN_EPS) * gm[q] + bt[q];
            o[q] = 0.5f * z * (1.f + erff(z * 0.70710678118654752f));
        }
        float4 h = *(float4*)&g_h[nid * 64 + cg * 4];
        h.x += o[0]; h.y += o[1]; h.z += o[2]; h.w += o[3];
        *(float4*)&g_h[nid * 64 + cg * 4] = h;
    }
}

// ---------------- pooling ----------------
// lin projection fused with pooled sum AND node counting
__global__ void lin_pool(const float* __restrict__ W, const float* __restrict__ bias,
                         const int* __restrict__ batch, float* __restrict__ pooled) {
    __shared__ float Ws[128][68];
    __shared__ float As[32][68];
    int t = threadIdx.x;            // 256
    int row0 = blockIdx.x * 32;

    for (int i = t; i < 128 * 64; i += 256) { int c = i >> 6, k = i & 63; Ws[c][k] = W[i]; }
    for (int i = t; i < 32 * 64; i += 256) {
        int r = i >> 6, k = i & 63; int gr = row0 + r;
        As[r][k] = (gr < N_NODES) ? g_h[gr * 64 + k] : 0.f;
    }
    __syncthreads();

    int c  = t & 127;
    int rb = t >> 7;
    float acc[16];
    #pragma unroll
    for (int r = 0; r < 16; r++) acc[r] = 0.f;

    #pragma unroll
    for (int k4 = 0; k4 < 16; k4++) {
        float4 w4 = *(const float4*)&Ws[c][k4 * 4];
        #pragma unroll
        for (int r = 0; r < 16; r++) {
            float4 a4 = *(const float4*)&As[rb * 16 + r][k4 * 4];
            acc[r] += w4.x * a4.x + w4.y * a4.y + w4.z * a4.z + w4.w * a4.w;
        }
    }
    float bb = bias[c];
    #pragma unroll
    for (int r = 0; r < 16; r++) {
        int gr = row0 + rb * 16 + r;
        if (gr < N_NODES) {
            atomicAdd(&pooled[batch[gr] * DOUT + c], acc[r] + bb);
            if (c == 0) atomicAdd(&g_cnt[batch[gr]], 1.f);
        }
    }
}

__global__ void finalize(float* __restrict__ out) {
    int idx = blockIdx.x * blockDim.x + threadIdx.x;
    if (idx >= G_GRAPHS * DOUT) return;
    out[idx] /= fmaxf(g_cnt[idx >> 7], 1.f);
}

// ---------------- launch ----------------
extern "C" void kernel_launch(void* const* d_in, const int* in_sizes, int n_in,
                              void* d_out, int out_size) {
    const float* x         = (const float*)d_in[0];
    const int*   ei        = (const int*)  d_in[1];
    const float* eattr     = (const float*)d_in[2];
    const int*   batch     = (const int*)  d_in[3];
    const float* emb_W     = (const float*)d_in[4];
    const float* emb_b     = (const float*)d_in[5];
    const float* Wl        = (const float*)d_in[6];
    const float* bl        = (const float*)d_in[7];
    const float* Wr        = (const float*)d_in[8];
    const float* br        = (const float*)d_in[9];
    const float* We        = (const float*)d_in[10];
    const float* att       = (const float*)d_in[11];
    const float* conv_bias = (const float*)d_in[12];
    const float* gamma     = (const float*)d_in[13];
    const float* beta      = (const float*)d_in[14];
    const float* mean      = (const float*)d_in[15];
    const float* var       = (const float*)d_in[16];
    const float* lin_W     = (const float*)d_in[17];
    const float* lin_b     = (const float*)d_in[18];
    float* out = (float*)d_out;

    const int GAT_BLOCKS = N_NODES / 8;                    // 6250
    const int EAW_BLOCKS = E_EDGES / EAW_EPB;              // 12500

    emb_hist<<<782 + 3125, 256>>>(x, emb_W, emb_b, ei, out);
    scan_scatter<<<1 + SCAT_BLOCKS, 1024>>>(ei, eattr);

    for (int l = 0; l < LAYERS; l++) {
        gemm_eaw16<<<EAW_BLOCKS, 256>>>(We + l * 1024);
        gemm_xlxr<<<XLR_GRID, 256>>>(Wl + l * 4096, bl + l * 64, Wr + l * 4096, br + l * 64);
        gat_layer<<<GAT_BLOCKS, 256>>>(att + l * 64, conv_bias + l * 64,
                                       gamma + l * 64, beta + l * 64, mean + l * 64, var + l * 64);
    }

    lin_pool<<<(N_NODES + 31) / 32, 256>>>(lin_W, lin_b, batch, out);
    finalize<<<(G_GRAPHS * DOUT + 255) / 256, 256>>>(out);
}